// round 16
// baseline (speedup 1.0000x reference)
#include <cuda_runtime.h>
#include <cuda_bf16.h>
#include <cstddef>

// out[i] = feat[i] + (mean_k feat[nbr[i,k]]) @ W^T + b
// Phase A: bf16 gather (1-line LDG.32s) -> tf32 agg in smem.
// Phase B: tf32 mma.sync.m16n8k8; B frags from repacked Wrep_g (2x LDG.128).
// fp32 residual epilogue. R15: faster convert, hoisted idx loads, reg bias.

#define THREADS 128
static constexpr int D    = 128;
static constexpr int KDEG = 32;
static constexpr int NPB  = 32;
static constexpr int NMAX = 100000;

static constexpr int AGG_STRIDE = 132;
static constexpr int AGG_FLOATS = NPB * AGG_STRIDE;
static constexpr int SMEM_BYTES = AGG_FLOATS * 4;   // 16,896 B -> 8 CTAs/SM

__device__ __align__(16) float         Wrep_g[4 * 16 * 32 * 8];       // 64 KB
__device__ __align__(16) __nv_bfloat16 featb_g[(size_t)NMAX * D];     // 25.6 MB

// --- Pre-kernel 1: repack W into per-(warp,k8,lane) fragment order, tf32-rounded.
__global__ void repack_kernel(const float* __restrict__ W)
{
    int idx = blockIdx.x * 256 + threadIdx.x;     // 0..16383
    int q    = idx & 7;
    int lane = (idx >> 3) & 31;
    int k8   = (idx >> 8) & 15;
    int w    = idx >> 12;
    int i  = q >> 2, nt = q & 3;
    int kc = lane & 3, m0 = lane >> 2;
    int j = 8 * k8 + kc + 4 * i;
    int d = w * 32 + nt * 8 + m0;
    float v = W[d * D + j];
    unsigned u;
    asm("cvt.rna.tf32.f32 %0, %1;" : "=r"(u) : "f"(v));
    Wrep_g[idx] = __uint_as_float(u);
}

// --- Pre-kernel 2: feat -> bf16, grid-stride at full occupancy ---
__global__ void convert_kernel(const float* __restrict__ feat, int total4)
{
    int stride = gridDim.x * blockDim.x;
    for (int i = blockIdx.x * blockDim.x + threadIdx.x; i < total4; i += stride) {
        float4 v = ((const float4*)feat)[i];
        __nv_bfloat162 lo = __float22bfloat162_rn(make_float2(v.x, v.y));
        __nv_bfloat162 hi = __float22bfloat162_rn(make_float2(v.z, v.w));
        ((uint2*)featb_g)[i] = make_uint2(*(unsigned*)&lo, *(unsigned*)&hi);
    }
}

__device__ __forceinline__ uint2 scale_tf32(float2 f) {
    const float s = 1.0f / 32.0f;
    unsigned lo, hi;
    float x = f.x * s, y = f.y * s;
    asm("cvt.rna.tf32.f32 %0, %1;" : "=r"(lo) : "f"(x));
    asm("cvt.rna.tf32.f32 %0, %1;" : "=r"(hi) : "f"(y));
    return make_uint2(lo, hi);
}

__global__ __launch_bounds__(THREADS, 8)
void subgconv_kernel(const float* __restrict__ feat,
                     const int* __restrict__ nbr,
                     const int* __restrict__ nidx,
                     const float* __restrict__ bias,
                     float* __restrict__ out,
                     int N)
{
    extern __shared__ float smem[];
    float* agg = smem;                   // [NPB][AGG_STRIDE]; reused as Dbuf

    const int tid  = threadIdx.x;
    const int lane = tid & 31;
    const int w    = tid >> 5;           // warp 0..3

    const int gbase = blockIdx.x * NPB;
    const unsigned* gb = (const unsigned*)featb_g;   // bf16x2 units; row = 64 units

    // ---- Phase A: warp w gathers+averages nodes gbase + w*8 .. +8 (bf16, pairs) ----
    #pragma unroll
    for (int nn = 0; nn < 8; nn += 2) {
        int n0 = gbase + w * 8 + nn;
        int n1 = n0 + 1;
        bool v0 = n0 < N, v1 = n1 < N;
        const int4* np0 = (const int4*)(nbr + (size_t)(v0 ? n0 : 0) * KDEG);
        const int4* np1 = (const int4*)(nbr + (size_t)(v1 ? n1 : 0) * KDEG);
        // Hoist all index loads for the pair (removes in-loop LDG-use stalls)
        int4 idx0[8], idx1[8];
        #pragma unroll
        for (int k4 = 0; k4 < 8; k4++) { idx0[k4] = np0[k4]; idx1[k4] = np1[k4]; }

        float2 a0l = make_float2(0.f,0.f), a0h = make_float2(0.f,0.f);
        float2 a1l = make_float2(0.f,0.f), a1h = make_float2(0.f,0.f);
        #pragma unroll
        for (int k4 = 0; k4 < 8; k4++) {
            int4 i0 = idx0[k4];
            int4 i1 = idx1[k4];
            unsigned u; float2 t; size_t b;
            #define ACC(idx, al, ah)                                          \
                b = (size_t)(idx) * 64 + lane;                                 \
                u = gb[b];      t = __bfloat1622float2(*(__nv_bfloat162*)&u);  \
                al.x += t.x; al.y += t.y;                                      \
                u = gb[b + 32]; t = __bfloat1622float2(*(__nv_bfloat162*)&u);  \
                ah.x += t.x; ah.y += t.y;
            ACC(i0.x, a0l, a0h)  ACC(i1.x, a1l, a1h)
            ACC(i0.y, a0l, a0h)  ACC(i1.y, a1l, a1h)
            ACC(i0.z, a0l, a0h)  ACC(i1.z, a1l, a1h)
            ACC(i0.w, a0l, a0h)  ACC(i1.w, a1l, a1h)
            #undef ACC
        }
        unsigned* au = (unsigned*)agg;
        if (v0) {
            int r = (w*8+nn) * AGG_STRIDE;
            *(uint2*)(au + r + 2*lane)      = scale_tf32(a0l);
            *(uint2*)(au + r + 64 + 2*lane) = scale_tf32(a0h);
        }
        if (v1) {
            int r = (w*8+nn+1) * AGG_STRIDE;
            *(uint2*)(au + r + 2*lane)      = scale_tf32(a1l);
            *(uint2*)(au + r + 64 + 2*lane) = scale_tf32(a1h);
        }
    }
    __syncthreads();

    // ---- Phase B: warp w covers d-slice [32w,32w+32) x 32 nodes, tf32 MMA ----
    {
        const int m0 = lane >> 2;
        const int kc = lane & 3;
        const int dw = w * 32;

        float c[2][4][4];
        #pragma unroll
        for (int mt = 0; mt < 2; mt++)
            #pragma unroll
            for (int nt = 0; nt < 4; nt++)
                #pragma unroll
                for (int i = 0; i < 4; i++) c[mt][nt][i] = 0.f;

        const unsigned* aggu = (const unsigned*)agg;
        const int abase = m0 * AGG_STRIDE + kc;
        const float4* wrep = (const float4*)Wrep_g + ((size_t)w * 16 * 32 + lane) * 2;

        #pragma unroll 1
        for (int k8 = 0; k8 < 16; k8++) {
            const unsigned* ak = aggu + abase + k8 * 8;
            unsigned a[2][4];
            #pragma unroll
            for (int mt = 0; mt < 2; mt++) {
                int mo = mt * 16 * AGG_STRIDE;
                a[mt][0] = ak[mo];
                a[mt][1] = ak[mo + 8 * AGG_STRIDE];
                a[mt][2] = ak[mo + 4];
                a[mt][3] = ak[mo + 8 * AGG_STRIDE + 4];
            }
            float4 f0 = wrep[k8 * 64];          // b[nt][0]
            float4 f1 = wrep[k8 * 64 + 1];      // b[nt][1]
            const float* b0 = &f0.x;
            const float* b1 = &f1.x;
            #pragma unroll
            for (int mt = 0; mt < 2; mt++)
                #pragma unroll
                for (int nt = 0; nt < 4; nt++) {
                    asm volatile(
                        "mma.sync.aligned.m16n8k8.row.col.f32.tf32.tf32.f32 "
                        "{%0,%1,%2,%3}, {%4,%5,%6,%7}, {%8,%9}, {%0,%1,%2,%3};"
                        : "+f"(c[mt][nt][0]), "+f"(c[mt][nt][1]),
                          "+f"(c[mt][nt][2]), "+f"(c[mt][nt][3])
                        : "r"(a[mt][0]), "r"(a[mt][1]), "r"(a[mt][2]), "r"(a[mt][3]),
                          "r"(__float_as_uint(b0[nt])), "r"(__float_as_uint(b1[nt])));
                }
        }
        __syncthreads();   // all agg reads complete -> reuse buffer as Dbuf

        #pragma unroll
        for (int mt = 0; mt < 2; mt++)
            #pragma unroll
            for (int nt = 0; nt < 4; nt++) {
                float* dp = agg + (m0 + mt*16) * AGG_STRIDE + dw + nt*8 + 2*kc;
                *(float2*)dp                    = make_float2(c[mt][nt][0], c[mt][nt][1]);
                *(float2*)(dp + 8 * AGG_STRIDE) = make_float2(c[mt][nt][2], c[mt][nt][3]);
            }
    }
    __syncthreads();

    // ---- Epilogue: warp w writes nodes w*8..+8: out = D + feat[nidx] + b (fp32) ----
    {
        float4 bv = *(const float4*)&bias[lane * 4];   // L1-resident after first CTA
        #pragma unroll
        for (int n = 0; n < 8; n++) {
            int nl   = w * 8 + n;
            int node = gbase + nl;
            if (node < N) {
                int r = nidx[node];
                float4 dv = *(const float4*)&agg[nl * AGG_STRIDE + 4 * lane];
                float4 fv = ((const float4*)feat)[(size_t)r * 32 + lane];
                float4 o = make_float4(dv.x + fv.x + bv.x, dv.y + fv.y + bv.y,
                                       dv.z + fv.z + bv.z, dv.w + fv.w + bv.w);
                ((float4*)out)[(size_t)node * 32 + lane] = o;
            }
        }
    }
}

extern "C" void kernel_launch(void* const* d_in, const int* in_sizes, int n_in,
                              void* d_out, int out_size)
{
    const float* feat = (const float*)d_in[0];
    const int*   nbr  = (const int*)d_in[1];
    const int*   nidx = (const int*)d_in[2];
    const float* W    = (const float*)d_in[3];
    const float* bias = (const float*)d_in[4];
    float*       out  = (float*)d_out;

    const int N = in_sizes[2];

    repack_kernel<<<64, 256>>>(W);

    const int total4 = (N * D) / 4;
    convert_kernel<<<1184, 256>>>(feat, total4);   // grid-stride, ~2.7 elems/thread

    cudaFuncSetAttribute(subgconv_kernel,
                         cudaFuncAttributeMaxDynamicSharedMemorySize, SMEM_BYTES);
    const int grid = (N + NPB - 1) / NPB;
    subgconv_kernel<<<grid, THREADS, SMEM_BYTES>>>(feat, nbr, nidx, bias, out, N);
}

// round 17
// speedup vs baseline: 1.2492x; 1.2492x over previous
#include <cuda_runtime.h>
#include <cuda_bf16.h>
#include <cstddef>

// out[i] = feat[i] + (mean_k feat[nbr[i,k]]) @ W^T + b
// Phase A: bf16 gather via LDG.64 + shift/mask convert + f32x2 accumulate.
// Phase B: tf32 mma.sync.m16n8k8; B frags from repacked Wrep_g (2x LDG.128).
// fp32 residual epilogue. Pre-kernels merged into one launch.

#define THREADS 128
static constexpr int D    = 128;
static constexpr int KDEG = 32;
static constexpr int NPB  = 32;
static constexpr int NMAX = 100000;

static constexpr int AGG_STRIDE = 132;
static constexpr int AGG_FLOATS = NPB * AGG_STRIDE;
static constexpr int SMEM_BYTES = AGG_FLOATS * 4;   // 16,896 B -> 8 CTAs/SM

__device__ __align__(16) float         Wrep_g[4 * 16 * 32 * 8];       // 64 KB
__device__ __align__(16) __nv_bfloat16 featb_g[(size_t)NMAX * D];     // 25.6 MB

// --- Merged pre-kernel: blocks 0..63 repack W (tf32), all blocks convert feat->bf16 ---
__global__ void prep_kernel(const float* __restrict__ W,
                            const float* __restrict__ feat, int total4)
{
    if (blockIdx.x < 64) {
        int idx = blockIdx.x * 256 + threadIdx.x;     // 0..16383
        int q    = idx & 7;
        int lane = (idx >> 3) & 31;
        int k8   = (idx >> 8) & 15;
        int w    = idx >> 12;
        int i  = q >> 2, nt = q & 3;
        int kc = lane & 3, m0 = lane >> 2;
        int j = 8 * k8 + kc + 4 * i;
        int d = w * 32 + nt * 8 + m0;
        float v = W[d * D + j];
        unsigned u;
        asm("cvt.rna.tf32.f32 %0, %1;" : "=r"(u) : "f"(v));
        Wrep_g[idx] = __uint_as_float(u);
    }
    int stride = gridDim.x * blockDim.x;
    for (int i = blockIdx.x * blockDim.x + threadIdx.x; i < total4; i += stride) {
        float4 v = ((const float4*)feat)[i];
        __nv_bfloat162 lo = __float22bfloat162_rn(make_float2(v.x, v.y));
        __nv_bfloat162 hi = __float22bfloat162_rn(make_float2(v.z, v.w));
        ((uint2*)featb_g)[i] = make_uint2(*(unsigned*)&lo, *(unsigned*)&hi);
    }
}

// Accumulate a bf16x2 word into a packed f32x2 accumulator: acc += {lo<<16, hi&msk}
__device__ __forceinline__ void acc_bf16x2(unsigned long long& acc, unsigned u) {
    unsigned long long p;
    asm("{\n\t"
        ".reg .b32 lo, hi;\n\t"
        "shl.b32 lo, %1, 16;\n\t"
        "and.b32 hi, %1, 0xffff0000;\n\t"
        "mov.b64 %0, {lo, hi};\n\t"
        "}" : "=l"(p) : "r"(u));
    asm("add.rn.f32x2 %0, %1, %2;" : "=l"(acc) : "l"(p), "l"(acc));
}

__device__ __forceinline__ uint2 scale_tf32(unsigned long long a) {
    const unsigned long long ss = 0x3D0000003D000000ULL;   // {1/32, 1/32}
    unsigned long long r;
    asm("mul.rn.f32x2 %0, %1, %2;" : "=l"(r) : "l"(a), "l"(ss));
    float2 f = *(float2*)&r;
    unsigned lo, hi;
    asm("cvt.rna.tf32.f32 %0, %1;" : "=r"(lo) : "f"(f.x));
    asm("cvt.rna.tf32.f32 %0, %1;" : "=r"(hi) : "f"(f.y));
    return make_uint2(lo, hi);
}

__global__ __launch_bounds__(THREADS, 8)
void subgconv_kernel(const float* __restrict__ feat,
                     const int* __restrict__ nbr,
                     const int* __restrict__ nidx,
                     const float* __restrict__ bias,
                     float* __restrict__ out,
                     int N)
{
    extern __shared__ float smem[];
    float* agg = smem;                   // [NPB][AGG_STRIDE]; reused as Dbuf

    const int tid  = threadIdx.x;
    const int lane = tid & 31;
    const int w    = tid >> 5;           // warp 0..3

    const int gbase = blockIdx.x * NPB;
    const uint2* gb2 = (const uint2*)featb_g;   // row = 32 uint2; lane -> dims [4l,4l+4)

    // ---- Phase A: warp w gathers+averages nodes gbase + w*8 .. +8 (bf16, pairs) ----
    #pragma unroll
    for (int nn = 0; nn < 8; nn += 2) {
        int n0 = gbase + w * 8 + nn;
        int n1 = n0 + 1;
        bool v0 = n0 < N, v1 = n1 < N;
        const int4* np0 = (const int4*)(nbr + (size_t)(v0 ? n0 : 0) * KDEG);
        const int4* np1 = (const int4*)(nbr + (size_t)(v1 ? n1 : 0) * KDEG);
        int4 idx0[8], idx1[8];
        #pragma unroll
        for (int k4 = 0; k4 < 8; k4++) { idx0[k4] = np0[k4]; idx1[k4] = np1[k4]; }

        // accumulators: x-chain = dims {4l,4l+1}, y-chain = dims {4l+2,4l+3}
        unsigned long long a0x = 0ull, a0y = 0ull, a1x = 0ull, a1y = 0ull;
        #pragma unroll
        for (int k4 = 0; k4 < 8; k4++) {
            int4 i0 = idx0[k4];
            int4 i1 = idx1[k4];
            uint2 u;
            #define ACC(idx, ax, ay)                         \
                u = gb2[(size_t)(idx) * 32 + lane];           \
                acc_bf16x2(ax, u.x);                          \
                acc_bf16x2(ay, u.y);
            ACC(i0.x, a0x, a0y)  ACC(i1.x, a1x, a1y)
            ACC(i0.y, a0x, a0y)  ACC(i1.y, a1x, a1y)
            ACC(i0.z, a0x, a0y)  ACC(i1.z, a1x, a1y)
            ACC(i0.w, a0x, a0y)  ACC(i1.w, a1x, a1y)
            #undef ACC
        }
        unsigned* au = (unsigned*)agg;
        if (v0) {
            uint2 px = scale_tf32(a0x), py = scale_tf32(a0y);
            *(uint4*)(au + (w*8+nn) * AGG_STRIDE + 4*lane) =
                make_uint4(px.x, px.y, py.x, py.y);
        }
        if (v1) {
            uint2 px = scale_tf32(a1x), py = scale_tf32(a1y);
            *(uint4*)(au + (w*8+nn+1) * AGG_STRIDE + 4*lane) =
                make_uint4(px.x, px.y, py.x, py.y);
        }
    }

    // Prefetch epilogue node indices (independent of MMA)
    const int nbase = gbase + w * 8;
    int4 nv0 = *(const int4*)&nidx[nbase];
    int4 nv1 = *(const int4*)&nidx[nbase + 4];
    __syncthreads();

    // ---- Phase B: warp w covers d-slice [32w,32w+32) x 32 nodes, tf32 MMA ----
    {
        const int m0 = lane >> 2;
        const int kc = lane & 3;
        const int dw = w * 32;

        float c[2][4][4];
        #pragma unroll
        for (int mt = 0; mt < 2; mt++)
            #pragma unroll
            for (int nt = 0; nt < 4; nt++)
                #pragma unroll
                for (int i = 0; i < 4; i++) c[mt][nt][i] = 0.f;

        const unsigned* aggu = (const unsigned*)agg;
        const int abase = m0 * AGG_STRIDE + kc;
        const float4* wrep = (const float4*)Wrep_g + ((size_t)w * 16 * 32 + lane) * 2;

        #pragma unroll 1
        for (int k8 = 0; k8 < 16; k8++) {
            const unsigned* ak = aggu + abase + k8 * 8;
            unsigned a[2][4];
            #pragma unroll
            for (int mt = 0; mt < 2; mt++) {
                int mo = mt * 16 * AGG_STRIDE;
                a[mt][0] = ak[mo];
                a[mt][1] = ak[mo + 8 * AGG_STRIDE];
                a[mt][2] = ak[mo + 4];
                a[mt][3] = ak[mo + 8 * AGG_STRIDE + 4];
            }
            float4 f0 = wrep[k8 * 64];          // b[nt][0]
            float4 f1 = wrep[k8 * 64 + 1];      // b[nt][1]
            const float* b0 = &f0.x;
            const float* b1 = &f1.x;
            #pragma unroll
            for (int mt = 0; mt < 2; mt++)
                #pragma unroll
                for (int nt = 0; nt < 4; nt++) {
                    asm volatile(
                        "mma.sync.aligned.m16n8k8.row.col.f32.tf32.tf32.f32 "
                        "{%0,%1,%2,%3}, {%4,%5,%6,%7}, {%8,%9}, {%0,%1,%2,%3};"
                        : "+f"(c[mt][nt][0]), "+f"(c[mt][nt][1]),
                          "+f"(c[mt][nt][2]), "+f"(c[mt][nt][3])
                        : "r"(a[mt][0]), "r"(a[mt][1]), "r"(a[mt][2]), "r"(a[mt][3]),
                          "r"(__float_as_uint(b0[nt])), "r"(__float_as_uint(b1[nt])));
                }
        }
        __syncthreads();   // all agg reads complete -> reuse buffer as Dbuf

        #pragma unroll
        for (int mt = 0; mt < 2; mt++)
            #pragma unroll
            for (int nt = 0; nt < 4; nt++) {
                float* dp = agg + (m0 + mt*16) * AGG_STRIDE + dw + nt*8 + 2*kc;
                *(float2*)dp                    = make_float2(c[mt][nt][0], c[mt][nt][1]);
                *(float2*)(dp + 8 * AGG_STRIDE) = make_float2(c[mt][nt][2], c[mt][nt][3]);
            }
    }
    __syncthreads();

    // ---- Epilogue: warp w writes nodes w*8..+8: out = D + feat[nidx] + b (fp32) ----
    {
        float4 bv = *(const float4*)&bias[lane * 4];   // L1-resident after first CTA
        int rr[8] = {nv0.x, nv0.y, nv0.z, nv0.w, nv1.x, nv1.y, nv1.z, nv1.w};
        #pragma unroll
        for (int n = 0; n < 8; n++) {
            int nl   = w * 8 + n;
            int node = gbase + nl;
            if (node < N) {
                float4 dv = *(const float4*)&agg[nl * AGG_STRIDE + 4 * lane];
                float4 fv = ((const float4*)feat)[(size_t)rr[n] * 32 + lane];
                float4 o = make_float4(dv.x + fv.x + bv.x, dv.y + fv.y + bv.y,
                                       dv.z + fv.z + bv.z, dv.w + fv.w + bv.w);
                ((float4*)out)[(size_t)node * 32 + lane] = o;
            }
        }
    }
}

extern "C" void kernel_launch(void* const* d_in, const int* in_sizes, int n_in,
                              void* d_out, int out_size)
{
    const float* feat = (const float*)d_in[0];
    const int*   nbr  = (const int*)d_in[1];
    const int*   nidx = (const int*)d_in[2];
    const float* W    = (const float*)d_in[3];
    const float* bias = (const float*)d_in[4];
    float*       out  = (float*)d_out;

    const int N = in_sizes[2];

    const int total4 = (N * D) / 4;
    prep_kernel<<<1184, 256>>>(W, feat, total4);

    cudaFuncSetAttribute(subgconv_kernel,
                         cudaFuncAttributeMaxDynamicSharedMemorySize, SMEM_BYTES);
    const int grid = (N + NPB - 1) / NPB;
    subgconv_kernel<<<grid, THREADS, SMEM_BYTES>>>(feat, nbr, nidx, bias, out, N);
}